// round 1
// baseline (speedup 1.0000x reference)
#include <cuda_runtime.h>
#include <math.h>

// ---------------- problem constants ----------------
#define Bdim 8
#define Kst 4
#define Lseq 1024
#define Ddim 512
#define Hn 8
#define HDdim 64
#define BLn (Bdim * Lseq)   // 8192
#define Tn (BLn * Kst)      // 32768
#define D3 (3 * Ddim)       // 1536

// output section offsets (floats)
#define OUT_FUSED 0
#define OUT_AP    4194304
#define OUT_WM    8388608
#define OUT_MF    12582912
#define OUT_AM    16777216
#define OUT_NSW   16809984

// ---------------- device scratch ----------------
__device__ float g_x[(size_t)Tn * Ddim];
__device__ float g_Q[(size_t)Tn * Ddim];
__device__ float g_K[(size_t)Tn * Ddim];
__device__ float g_V[(size_t)Tn * Ddim];
__device__ float g_AO[(size_t)BLn * Ddim];     // swr-pooled attention output (pre-Wo)
__device__ float g_G[(size_t)BLn * D3];        // layernormed gate_in
__device__ float g_H1[(size_t)BLn * Ddim];     // gelu hidden
__device__ float g_GATE[(size_t)BLn * Ddim];   // sigmoid gate
__device__ float g_swr[BLn * Kst];
__device__ float g_nsw[Bdim * Kst];
__device__ float g_lognsw[Bdim * Kst];
__device__ int   g_mask_u8;

// ---------------- mask dtype detection ----------------
// If masks are stored as 1-byte bools, interpreting the first 8192 int32 words
// (32768 bytes -- safe under both layouts) yields packed values outside {0,1}
// with overwhelming probability for random data. If int32, all are 0/1.
__global__ void detect_mask_kernel(const void* rm) {
    const int* p = (const int*)rm;
    int bad = 0;
    for (int i = threadIdx.x; i < 8192; i += 256) {
        int v = p[i];
        if (v != 0 && v != 1) bad = 1;
    }
    bad = __syncthreads_or(bad);
    if (threadIdx.x == 0) g_mask_u8 = bad;
}

__device__ __forceinline__ bool mask_at(const void* p, int idx, int u8) {
    return u8 ? (((const unsigned char*)p)[idx] != 0)
              : (((const int*)p)[idx] != 0);
}

// ---------------- nsw ----------------
__global__ void nsw_kernel(const float* __restrict__ sw, const void* __restrict__ pm,
                           float* __restrict__ out_nsw) {
    int b = threadIdx.x;
    if (b >= Bdim) return;
    int u8 = g_mask_u8;
    float w[Kst], pres[Kst];
    float denom = 0.f, psum = 0.f;
#pragma unroll
    for (int k = 0; k < Kst; k++) {
        pres[k] = mask_at(pm, b * Kst + k, u8) ? 1.f : 0.f;
        w[k] = sw[b * Kst + k] * pres[k];
        denom += w[k];
        psum += pres[k];
    }
#pragma unroll
    for (int k = 0; k < Kst; k++) {
        float nswk = (denom > 1e-8f) ? (w[k] / fmaxf(denom, 1e-8f))
                                     : (pres[k] / fmaxf(psum, 1.f));
        g_nsw[b * Kst + k] = nswk;
        g_lognsw[b * Kst + k] = logf(fmaxf(nswk, 1e-8f));
        out_nsw[b * Kst + k] = nswk;
    }
}

// ---------------- build x, weighted_mean, max_feat, swr ----------------
__global__ void __launch_bounds__(512) build_x_kernel(
    const float* __restrict__ sr, const void* __restrict__ rm,
    const void* __restrict__ pm, const int* __restrict__ roles,
    const float* __restrict__ remb, float* __restrict__ dout) {
    int bl = blockIdx.x;
    int b = bl >> 10;
    int l = bl & 1023;
    int d = threadIdx.x;
    int u8 = g_mask_u8;

    bool vd[Kst];
    float swr[Kst];
    float ssum = 0.f;
#pragma unroll
    for (int k = 0; k < Kst; k++) {
        bool v = mask_at(rm, (b * Kst + k) * Lseq + l, u8) && mask_at(pm, b * Kst + k, u8);
        vd[k] = v;
        swr[k] = v ? g_nsw[b * Kst + k] : 0.f;
        ssum += swr[k];
    }
    float inv = 1.f / fmaxf(ssum, 1e-8f);

    float wm = 0.f, mx = -1e9f;
    bool any = false;
#pragma unroll
    for (int k = 0; k < Kst; k++) {
        swr[k] *= inv;
        float xv = 0.f;
        if (vd[k]) {
            int role = max(roles[b * Kst + k], 0);
            xv = sr[(((size_t)(b * Kst + k)) * Lseq + l) * Ddim + d] + remb[role * Ddim + d];
            any = true;
            mx = fmaxf(mx, xv);
        }
        g_x[((size_t)bl * Kst + k) * Ddim + d] = xv;
        wm += swr[k] * xv;
    }
    dout[OUT_WM + (size_t)bl * Ddim + d] = wm;
    dout[OUT_MF + (size_t)bl * Ddim + d] = any ? mx : 0.f;
    if (d < Kst) g_swr[bl * Kst + d] = swr[d];
}

// ---------------- fp32 GEMM: C[M,N] = A[M,K] @ B[N,K]^T (+epilogue) ----------------
// EPI: 0 none, 1 bias+gelu(exact), 2 bias+sigmoid
template <int EPI>
__global__ void __launch_bounds__(256) gemm_abT(
    const float* __restrict__ A, const float* __restrict__ B,
    const float* __restrict__ bias, float* __restrict__ C,
    int M, int N, int K) {
    __shared__ float As[16][64];
    __shared__ float Bs[16][64];
    const int tid = threadIdx.x;
    const int tx = tid & 15;
    const int ty = tid >> 4;
    const int lr = tid >> 2;          // 0..63
    const int lc = (tid & 3) << 2;    // 0,4,8,12
    const size_t bm = (size_t)blockIdx.y * 64;
    const int bn = blockIdx.x * 64;

    const float* Arow = A + (bm + lr) * (size_t)K + lc;
    const float* Brow = B + (size_t)(bn + lr) * K + lc;

    float acc[4][4] = {};
    for (int k0 = 0; k0 < K; k0 += 16) {
        float4 a = *(const float4*)(Arow + k0);
        float4 bq = *(const float4*)(Brow + k0);
        As[lc + 0][lr] = a.x; As[lc + 1][lr] = a.y;
        As[lc + 2][lr] = a.z; As[lc + 3][lr] = a.w;
        Bs[lc + 0][lr] = bq.x; Bs[lc + 1][lr] = bq.y;
        Bs[lc + 2][lr] = bq.z; Bs[lc + 3][lr] = bq.w;
        __syncthreads();
#pragma unroll
        for (int kk = 0; kk < 16; kk++) {
            float4 av = *(const float4*)(&As[kk][ty << 2]);
            float4 bv = *(const float4*)(&Bs[kk][tx << 2]);
            acc[0][0] += av.x * bv.x; acc[0][1] += av.x * bv.y;
            acc[0][2] += av.x * bv.z; acc[0][3] += av.x * bv.w;
            acc[1][0] += av.y * bv.x; acc[1][1] += av.y * bv.y;
            acc[1][2] += av.y * bv.z; acc[1][3] += av.y * bv.w;
            acc[2][0] += av.z * bv.x; acc[2][1] += av.z * bv.y;
            acc[2][2] += av.z * bv.z; acc[2][3] += av.z * bv.w;
            acc[3][0] += av.w * bv.x; acc[3][1] += av.w * bv.y;
            acc[3][2] += av.w * bv.z; acc[3][3] += av.w * bv.w;
        }
        __syncthreads();
    }

#pragma unroll
    for (int i = 0; i < 4; i++) {
        size_t row = bm + (ty << 2) + i;
        float r[4];
#pragma unroll
        for (int j = 0; j < 4; j++) r[j] = acc[i][j];
        if (EPI >= 1) {
#pragma unroll
            for (int j = 0; j < 4; j++) r[j] += bias[bn + (tx << 2) + j];
        }
        if (EPI == 1) {
#pragma unroll
            for (int j = 0; j < 4; j++)
                r[j] = 0.5f * r[j] * (1.f + erff(r[j] * 0.70710678118654752f));
        }
        if (EPI == 2) {
#pragma unroll
            for (int j = 0; j < 4; j++) r[j] = 1.f / (1.f + expf(-r[j]));
        }
        float4 o;
        o.x = r[0]; o.y = r[1]; o.z = r[2]; o.w = r[3];
        *(float4*)(C + row * (size_t)N + bn + (tx << 2)) = o;
    }
}

// ---------------- attention: 4x4 per (b,l,h); pooled output + attn_mean ----------------
__global__ void __launch_bounds__(256) attn_kernel(
    const void* __restrict__ rm, const void* __restrict__ pm,
    float* __restrict__ dout) {
    int bl = blockIdx.x;
    int b = bl >> 10;
    int l = bl & 1023;
    int warp = threadIdx.x >> 5;
    int lane = threadIdx.x & 31;
    __shared__ float am[Kst];
    if (threadIdx.x < Kst) am[threadIdx.x] = 0.f;
    __syncthreads();
    int u8 = g_mask_u8;

    float2 q[Kst], kk[Kst], vv[Kst];
    float ln_w[Kst], swr[Kst];
    bool vd[Kst];
    size_t base = ((size_t)bl * Kst) * Ddim + warp * HDdim + lane * 2;
#pragma unroll
    for (int s = 0; s < Kst; s++) {
        q[s]  = *(const float2*)(g_Q + base + (size_t)s * Ddim);
        kk[s] = *(const float2*)(g_K + base + (size_t)s * Ddim);
        vv[s] = *(const float2*)(g_V + base + (size_t)s * Ddim);
        vd[s] = mask_at(rm, (b * Kst + s) * Lseq + l, u8) && mask_at(pm, b * Kst + s, u8);
        ln_w[s] = g_lognsw[b * Kst + s];
        swr[s]  = g_swr[bl * Kst + s];
    }

    float dot[Kst][Kst];
#pragma unroll
    for (int i = 0; i < Kst; i++) {
#pragma unroll
        for (int j = 0; j < Kst; j++) {
            float p = q[i].x * kk[j].x + q[i].y * kk[j].y;
#pragma unroll
            for (int o = 16; o; o >>= 1) p += __shfl_xor_sync(0xffffffffu, p, o);
            dot[i][j] = p;
        }
    }

    float a[Kst][Kst];
#pragma unroll
    for (int i = 0; i < Kst; i++) {
        float lm[Kst] = {0.f, 0.f, 0.f, 0.f};
        float m = -3.4e38f;
#pragma unroll
        for (int j = 0; j < Kst; j++) {
            if (vd[j]) {
                lm[j] = dot[i][j] * 0.125f + ln_w[j];
                m = fmaxf(m, lm[j]);
            }
        }
        float ssum = 0.f;
#pragma unroll
        for (int j = 0; j < Kst; j++) {
            float e = vd[j] ? expf(lm[j] - m) : 0.f;
            a[i][j] = e;
            ssum += e;
        }
        float invs = (ssum > 0.f) ? (1.f / ssum) : 0.f;
#pragma unroll
        for (int j = 0; j < Kst; j++) a[i][j] *= invs;
    }

    // pool over query-state i with swr (commutes with Wo later)
    float px = 0.f, py = 0.f;
#pragma unroll
    for (int i = 0; i < Kst; i++) {
        float ox = 0.f, oy = 0.f;
#pragma unroll
        for (int j = 0; j < Kst; j++) {
            ox += a[i][j] * vv[j].x;
            oy += a[i][j] * vv[j].y;
        }
        px += swr[i] * ox;
        py += swr[i] * oy;
    }
    size_t obase = (size_t)bl * Ddim + warp * HDdim + lane * 2;
    g_AO[obase] = px;
    g_AO[obase + 1] = py;

    if (lane == 0) {
#pragma unroll
        for (int j = 0; j < Kst; j++)
            atomicAdd(&am[j], a[0][j] + a[1][j] + a[2][j] + a[3][j]);
    }
    __syncthreads();
    if (threadIdx.x < Kst)
        dout[OUT_AM + (size_t)bl * Kst + threadIdx.x] = am[threadIdx.x] * (1.f / 32.f);
}

// ---------------- block reduction ----------------
__device__ __forceinline__ float block_sum(float v, float* red) {
    int lane = threadIdx.x & 31, w = threadIdx.x >> 5;
#pragma unroll
    for (int o = 16; o; o >>= 1) v += __shfl_xor_sync(0xffffffffu, v, o);
    __syncthreads();
    if (lane == 0) red[w] = v;
    __syncthreads();
    if (threadIdx.x == 0) {
        float t = 0.f;
        int nw = (blockDim.x + 31) >> 5;
        for (int i = 0; i < nw; i++) t += red[i];
        red[8] = t;
    }
    __syncthreads();
    return red[8];
}

// ---------------- layernorm of gate_in (1536) ----------------
__global__ void __launch_bounds__(256) ln_gatein_kernel(
    const float* __restrict__ dro, const float* __restrict__ g,
    const float* __restrict__ bb) {
    int bl = blockIdx.x;
    __shared__ float buf[D3];
    __shared__ float red[9];
    float s = 0.f;
    for (int c = threadIdx.x; c < D3; c += 256) {
        float v;
        if (c < Ddim)          v = dro[OUT_AP + (size_t)bl * Ddim + c];
        else if (c < 2 * Ddim) v = dro[OUT_WM + (size_t)bl * Ddim + (c - Ddim)];
        else                   v = dro[OUT_MF + (size_t)bl * Ddim + (c - 2 * Ddim)];
        buf[c] = v;
        s += v;
    }
    s = block_sum(s, red);
    float mu = s * (1.f / D3);
    float sq = 0.f;
    for (int c = threadIdx.x; c < D3; c += 256) {
        float d = buf[c] - mu;
        sq += d * d;
    }
    sq = block_sum(sq, red);
    float rs = rsqrtf(sq * (1.f / D3) + 1e-5f);
    for (int c = threadIdx.x; c < D3; c += 256)
        g_G[(size_t)bl * D3 + c] = (buf[c] - mu) * rs * g[c] + bb[c];
}

// ---------------- final fuse + layernorm(512) ----------------
__global__ void __launch_bounds__(256) ln_final_kernel(
    float* __restrict__ dout, const float* __restrict__ ng,
    const float* __restrict__ nb) {
    int bl = blockIdx.x;
    __shared__ float buf[Ddim];
    __shared__ float red[9];
    float s = 0.f;
    for (int d = threadIdx.x; d < Ddim; d += 256) {
        float gate = g_GATE[(size_t)bl * Ddim + d];
        float ap = dout[OUT_AP + (size_t)bl * Ddim + d];
        float wm = dout[OUT_WM + (size_t)bl * Ddim + d];
        float mf = dout[OUT_MF + (size_t)bl * Ddim + d];
        float y = gate * 0.5f * (ap + wm) + (1.f - gate) * mf + wm;
        buf[d] = y;
        s += y;
    }
    s = block_sum(s, red);
    float mu = s * (1.f / Ddim);
    float sq = 0.f;
    for (int d = threadIdx.x; d < Ddim; d += 256) {
        float dd = buf[d] - mu;
        sq += dd * dd;
    }
    sq = block_sum(sq, red);
    float rs = rsqrtf(sq * (1.f / Ddim) + 1e-5f);
    for (int d = threadIdx.x; d < Ddim; d += 256)
        dout[OUT_FUSED + (size_t)bl * Ddim + d] = (buf[d] - mu) * rs * ng[d] + nb[d];
}

// ---------------- launch ----------------
extern "C" void kernel_launch(void* const* d_in, const int* in_sizes, int n_in,
                              void* d_out, int out_size) {
    const float* sr    = (const float*)d_in[0];
    const void*  rmask = d_in[1];
    const float* sw    = (const float*)d_in[2];
    const int*   roles = (const int*)d_in[3];
    const void*  pmask = d_in[4];
    const float* remb  = (const float*)d_in[5];
    const float* Wq    = (const float*)d_in[6];
    const float* Wk    = (const float*)d_in[7];
    const float* Wv    = (const float*)d_in[8];
    const float* Wo    = (const float*)d_in[9];
    const float* ln1g  = (const float*)d_in[10];
    const float* ln1b  = (const float*)d_in[11];
    const float* Wg1   = (const float*)d_in[12];
    const float* bg1   = (const float*)d_in[13];
    const float* Wg2   = (const float*)d_in[14];
    const float* bg2   = (const float*)d_in[15];
    const float* ng    = (const float*)d_in[16];
    const float* nb    = (const float*)d_in[17];
    float* dout = (float*)d_out;

    float *px, *pq, *pk, *pv, *pao, *pg, *ph1, *pgate;
    cudaGetSymbolAddress((void**)&px, g_x);
    cudaGetSymbolAddress((void**)&pq, g_Q);
    cudaGetSymbolAddress((void**)&pk, g_K);
    cudaGetSymbolAddress((void**)&pv, g_V);
    cudaGetSymbolAddress((void**)&pao, g_AO);
    cudaGetSymbolAddress((void**)&pg, g_G);
    cudaGetSymbolAddress((void**)&ph1, g_H1);
    cudaGetSymbolAddress((void**)&pgate, g_GATE);

    detect_mask_kernel<<<1, 256>>>(rmask);
    nsw_kernel<<<1, 32>>>(sw, pmask, dout + OUT_NSW);
    build_x_kernel<<<BLn, 512>>>(sr, rmask, pmask, roles, remb, dout);

    dim3 gq(Ddim / 64, Tn / 64);
    gemm_abT<0><<<gq, 256>>>(px, Wq, nullptr, pq, Tn, Ddim, Ddim);
    gemm_abT<0><<<gq, 256>>>(px, Wk, nullptr, pk, Tn, Ddim, Ddim);
    gemm_abT<0><<<gq, 256>>>(px, Wv, nullptr, pv, Tn, Ddim, Ddim);

    attn_kernel<<<BLn, 256>>>(rmask, pmask, dout);

    dim3 go(Ddim / 64, BLn / 64);
    gemm_abT<0><<<go, 256>>>(pao, Wo, nullptr, dout + OUT_AP, BLn, Ddim, Ddim);

    ln_gatein_kernel<<<BLn, 256>>>(dout, ln1g, ln1b);
    gemm_abT<1><<<go, 256>>>(pg, Wg1, bg1, ph1, BLn, Ddim, D3);
    gemm_abT<2><<<go, 256>>>(ph1, Wg2, bg2, pgate, BLn, Ddim, Ddim);
    ln_final_kernel<<<BLn, 256>>>(dout, ng, nb);
}

// round 3
// speedup vs baseline: 2.4029x; 2.4029x over previous
#include <cuda_runtime.h>
#include <cuda_bf16.h>
#include <math.h>
#include <stdint.h>

// ---------------- problem constants ----------------
#define Bdim 8
#define Kst 4
#define Lseq 1024
#define Ddim 512
#define Hn 8
#define HDdim 64
#define BLn 8192
#define Tn 32768
#define D3 1536

#define OUT_FUSED 0
#define OUT_AP    4194304
#define OUT_WM    8388608
#define OUT_MF    12582912
#define OUT_AM    16777216
#define OUT_NSW   16809984

// ---------------- device scratch ----------------
// split layout A-side rows: [hi(0:K) | lo(K:2K) | hi(2K:3K)]
// split layout B-side rows: [hi | hi | lo]  => A'.B' = hi.hi + lo.hi + hi.lo
__device__ __nv_bfloat16 g_Xs[(size_t)Tn * 1536];
__device__ float         g_QKV[(size_t)Tn * 1536];
__device__ __nv_bfloat16 g_AOs[(size_t)BLn * 1536];
__device__ __nv_bfloat16 g_Gs[(size_t)BLn * 4608];
__device__ __nv_bfloat16 g_H1s[(size_t)BLn * 1536];
__device__ float         g_GATE[(size_t)BLn * Ddim];
__device__ __nv_bfloat16 g_Ws1[1536 * 1536];
__device__ __nv_bfloat16 g_Wso[512 * 1536];
__device__ __nv_bfloat16 g_Wsg1[512 * 4608];
__device__ __nv_bfloat16 g_Wsg2[512 * 1536];
__device__ float g_swr[BLn * Kst];
__device__ float g_nsw[Bdim * Kst];
__device__ float g_lognsw[Bdim * Kst];
__device__ int   g_mask_u8;

// ---------------- helpers ----------------
__device__ __forceinline__ uint32_t smem_u32(const void* p) {
    uint32_t a;
    asm("{ .reg .u64 t; cvta.to.shared.u64 t, %1; cvt.u32.u64 %0, t; }" : "=r"(a) : "l"(p));
    return a;
}
__device__ __forceinline__ void split2(float v, __nv_bfloat16& hi, __nv_bfloat16& lo) {
    hi = __float2bfloat16(v);
    lo = __float2bfloat16(v - __bfloat162float(hi));
}
__device__ __forceinline__ void ldsm_x4(uint32_t& r0, uint32_t& r1, uint32_t& r2,
                                        uint32_t& r3, uint32_t addr) {
    asm volatile("ldmatrix.sync.aligned.m8n8.x4.shared.b16 {%0,%1,%2,%3}, [%4];"
                 : "=r"(r0), "=r"(r1), "=r"(r2), "=r"(r3) : "r"(addr));
}
__device__ __forceinline__ void mma16816(float* c, const uint32_t* a, const uint32_t* b) {
    asm volatile(
        "mma.sync.aligned.m16n8k16.row.col.f32.bf16.bf16.f32 "
        "{%0,%1,%2,%3}, {%4,%5,%6,%7}, {%8,%9}, {%0,%1,%2,%3};"
        : "+f"(c[0]), "+f"(c[1]), "+f"(c[2]), "+f"(c[3])
        : "r"(a[0]), "r"(a[1]), "r"(a[2]), "r"(a[3]), "r"(b[0]), "r"(b[1]));
}
__device__ __forceinline__ uint32_t swz(uint32_t off) {
    return off ^ ((off >> 3) & 0x70);
}

// ---------------- mask dtype detection ----------------
__global__ void detect_mask_kernel(const void* rm) {
    const int* p = (const int*)rm;
    int bad = 0;
    for (int i = threadIdx.x; i < 8192; i += 256) {
        int v = p[i];
        if (v != 0 && v != 1) bad = 1;
    }
    bad = __syncthreads_or(bad);
    if (threadIdx.x == 0) g_mask_u8 = bad;
}
__device__ __forceinline__ bool mask_at(const void* p, int idx, int u8) {
    return u8 ? (((const unsigned char*)p)[idx] != 0) : (((const int*)p)[idx] != 0);
}

// ---------------- nsw ----------------
__global__ void nsw_kernel(const float* __restrict__ sw, const void* __restrict__ pm,
                           float* __restrict__ out_nsw) {
    int b = threadIdx.x;
    if (b >= Bdim) return;
    int u8 = g_mask_u8;
    float w[Kst], pres[Kst];
    float denom = 0.f, psum = 0.f;
#pragma unroll
    for (int k = 0; k < Kst; k++) {
        pres[k] = mask_at(pm, b * Kst + k, u8) ? 1.f : 0.f;
        w[k] = sw[b * Kst + k] * pres[k];
        denom += w[k];
        psum += pres[k];
    }
#pragma unroll
    for (int k = 0; k < Kst; k++) {
        float nswk = (denom > 1e-8f) ? (w[k] / fmaxf(denom, 1e-8f))
                                     : (pres[k] / fmaxf(psum, 1.f));
        g_nsw[b * Kst + k] = nswk;
        g_lognsw[b * Kst + k] = logf(fmaxf(nswk, 1e-8f));
        out_nsw[b * Kst + k] = nswk;
    }
}

// ---------------- build split-x, weighted_mean, max_feat, swr ----------------
__global__ void __launch_bounds__(512) build_x_kernel(
    const float* __restrict__ sr, const void* __restrict__ rm,
    const void* __restrict__ pm, const int* __restrict__ roles,
    const float* __restrict__ remb, float* __restrict__ dout) {
    int bl = blockIdx.x;
    int b = bl >> 10;
    int l = bl & 1023;
    int d = threadIdx.x;
    int u8 = g_mask_u8;

    bool vd[Kst];
    float swr[Kst];
    float ssum = 0.f;
#pragma unroll
    for (int k = 0; k < Kst; k++) {
        bool v = mask_at(rm, (b * Kst + k) * Lseq + l, u8) && mask_at(pm, b * Kst + k, u8);
        vd[k] = v;
        swr[k] = v ? g_nsw[b * Kst + k] : 0.f;
        ssum += swr[k];
    }
    float inv = 1.f / fmaxf(ssum, 1e-8f);

    float wm = 0.f, mx = -1e9f;
    bool any = false;
#pragma unroll
    for (int k = 0; k < Kst; k++) {
        swr[k] *= inv;
        float xv = 0.f;
        if (vd[k]) {
            int role = max(roles[b * Kst + k], 0);
            xv = sr[(((size_t)(b * Kst + k)) * Lseq + l) * Ddim + d] + remb[role * Ddim + d];
            any = true;
            mx = fmaxf(mx, xv);
        }
        __nv_bfloat16 hi, lo;
        split2(xv, hi, lo);
        size_t row = (size_t)(bl * Kst + k) * 1536;
        g_Xs[row + d] = hi;
        g_Xs[row + 512 + d] = lo;
        g_Xs[row + 1024 + d] = hi;
        wm += swr[k] * xv;
    }
    dout[OUT_WM + (size_t)bl * Ddim + d] = wm;
    dout[OUT_MF + (size_t)bl * Ddim + d] = any ? mx : 0.f;
    if (d < Kst) g_swr[bl * Kst + d] = swr[d];
}

// ---------------- weight splitter: out[N x 3K] = [hi | hi | lo] ----------------
__global__ void split_w_kernel(const float* __restrict__ W, __nv_bfloat16* __restrict__ out,
                               int Nn, int Kk) {
    int idx = blockIdx.x * 256 + threadIdx.x;
    if (idx >= Nn * Kk) return;
    int n = idx / Kk, k = idx - n * Kk;
    float v = W[idx];
    __nv_bfloat16 hi, lo;
    split2(v, hi, lo);
    __nv_bfloat16* row = out + (size_t)n * 3 * Kk;
    row[k] = hi;
    row[Kk + k] = hi;
    row[2 * Kk + k] = lo;
}

// ---------------- HMMA bf16 GEMM: C[M,N] = A[M,K'] @ B[N,K']^T ----------------
// 128x128 CTA tile; 8 warps = 2(m) x 4(n); warp 64x32; mma.m16n8k16.
// K-chunk 64 bf16 (128B rows, SW128 swizzle), double-buffered smem.
// EPI 0: fp32 store (ldc). EPI 1: bias+gelu -> split bf16 (ld 1536).
// EPI 2: bias+sigmoid -> fp32 (ld 512).
#define GSM_BYTES 65536

template <int EPI>
__global__ void __launch_bounds__(256) gemm_mma(
    const __nv_bfloat16* __restrict__ A, const __nv_bfloat16* __restrict__ B,
    const float* __restrict__ bias, float* __restrict__ Cf,
    __nv_bfloat16* __restrict__ Cb, int K, int ldc) {
    extern __shared__ __align__(1024) char smem[];
    uint32_t sA0 = smem_u32(smem);           // buf0: A 16K, B 16K; buf1 at +32K
    int tid = threadIdx.x;
    int wid = tid >> 5, lane = tid & 31;
    const int wm = wid >> 2, wn = wid & 3;

    const size_t bm = (size_t)blockIdx.y * 128;
    const int bn = blockIdx.x * 128;
    const int seg = tid & 7;
    const int r0 = tid >> 3;

    const __nv_bfloat16* Ab = A + (bm + r0) * (size_t)K + seg * 8;
    const __nv_bfloat16* Bb = B + (size_t)(bn + r0) * K + seg * 8;

    uint4 ra[4], rb[4];
    auto ldg = [&](int kc) {
#pragma unroll
        for (int i = 0; i < 4; i++) {
            ra[i] = *(const uint4*)(Ab + (size_t)(i * 32) * K + kc);
            rb[i] = *(const uint4*)(Bb + (size_t)(i * 32) * K + kc);
        }
    };
    auto sts = [&](int buf) {
        char* pa = smem + buf * 32768;
        char* pb = pa + 16384;
#pragma unroll
        for (int i = 0; i < 4; i++) {
            uint32_t sw = swz((r0 + i * 32) * 128 + seg * 16);
            *(uint4*)(pa + sw) = ra[i];
            *(uint4*)(pb + sw) = rb[i];
        }
    };

    float acc[4][4][4];
#pragma unroll
    for (int i = 0; i < 4; i++)
#pragma unroll
        for (int j = 0; j < 4; j++)
#pragma unroll
            for (int q = 0; q < 4; q++) acc[i][j][q] = 0.f;

    // ldmatrix base offsets (per kstep add 32 bytes)
    const uint32_t aRow = wm * 64 + (lane & 15);
    const uint32_t aColB = (lane >> 4) << 4;
    const uint32_t bRow = wn * 32 + (lane & 7) + ((lane >> 4) << 3);
    const uint32_t bColB = ((lane >> 3) & 1) << 4;

    const int NC = K >> 6;
    ldg(0);
    sts(0);
    __syncthreads();

    for (int c = 0; c < NC; c++) {
        int buf = c & 1;
        if (c + 1 < NC) ldg((c + 1) << 6);

        uint32_t Abuf = sA0 + buf * 32768;
        uint32_t Bbuf = Abuf + 16384;
#pragma unroll
        for (int ks = 0; ks < 4; ks++) {
            uint32_t a[4][4], b[4][2];
#pragma unroll
            for (int mt = 0; mt < 4; mt++) {
                uint32_t off = (aRow + mt * 16) * 128 + ks * 32 + aColB;
                ldsm_x4(a[mt][0], a[mt][1], a[mt][2], a[mt][3], Abuf + swz(off));
            }
#pragma unroll
            for (int p = 0; p < 2; p++) {
                uint32_t off = (bRow + p * 16) * 128 + ks * 32 + bColB;
                ldsm_x4(b[2 * p][0], b[2 * p][1], b[2 * p + 1][0], b[2 * p + 1][1],
                        Bbuf + swz(off));
            }
#pragma unroll
            for (int mt = 0; mt < 4; mt++)
#pragma unroll
                for (int nt = 0; nt < 4; nt++)
                    mma16816(acc[mt][nt], a[mt], b[nt]);
        }

        if (c + 1 < NC) {
            __syncthreads();
            sts(buf ^ 1);
            __syncthreads();
        }
    }

    // epilogue
    const int g = lane >> 2, t = lane & 3;
#pragma unroll
    for (int mt = 0; mt < 4; mt++) {
#pragma unroll
        for (int half = 0; half < 2; half++) {
            size_t grow = bm + wm * 64 + mt * 16 + g + half * 8;
#pragma unroll
            for (int nt = 0; nt < 4; nt++) {
                int col = bn + wn * 32 + nt * 8 + t * 2;
                float v0 = acc[mt][nt][half * 2 + 0];
                float v1 = acc[mt][nt][half * 2 + 1];
                if (EPI == 0) {
                    float2 o = make_float2(v0, v1);
                    *(float2*)(Cf + grow * (size_t)ldc + col) = o;
                } else if (EPI == 1) {
                    v0 += bias[col];
                    v1 += bias[col + 1];
                    v0 = 0.5f * v0 * (1.f + erff(v0 * 0.70710678118654752f));
                    v1 = 0.5f * v1 * (1.f + erff(v1 * 0.70710678118654752f));
                    __nv_bfloat16 h0, l0, h1, l1;
                    split2(v0, h0, l0);
                    split2(v1, h1, l1);
                    size_t o = grow * 1536 + col;
                    *(__nv_bfloat162*)(Cb + o)        = __nv_bfloat162(h0, h1);
                    *(__nv_bfloat162*)(Cb + o + 512)  = __nv_bfloat162(l0, l1);
                    *(__nv_bfloat162*)(Cb + o + 1024) = __nv_bfloat162(h0, h1);
                } else {
                    v0 += bias[col];
                    v1 += bias[col + 1];
                    float2 o;
                    o.x = 1.f / (1.f + expf(-v0));
                    o.y = 1.f / (1.f + expf(-v1));
                    *(float2*)(Cf + grow * 512 + col) = o;
                }
            }
        }
    }
}

// ---------------- attention: 4x4 per (b,l,h); pooled split output + attn_mean ----------------
__global__ void __launch_bounds__(256) attn_kernel(
    const void* __restrict__ rm, const void* __restrict__ pm,
    float* __restrict__ dout) {
    int bl = blockIdx.x;
    int b = bl >> 10;
    int l = bl & 1023;
    int warp = threadIdx.x >> 5;
    int lane = threadIdx.x & 31;
    __shared__ float am[Kst];
    if (threadIdx.x < Kst) am[threadIdx.x] = 0.f;
    __syncthreads();
    int u8 = g_mask_u8;

    float2 q[Kst], kk[Kst], vv[Kst];
    float ln_w[Kst], swr[Kst];
    bool vd[Kst];
    int col = warp * HDdim + lane * 2;
#pragma unroll
    for (int s = 0; s < Kst; s++) {
        size_t rbase = (size_t)(bl * Kst + s) * 1536 + col;
        q[s]  = *(const float2*)(g_QKV + rbase);
        kk[s] = *(const float2*)(g_QKV + rbase + 512);
        vv[s] = *(const float2*)(g_QKV + rbase + 1024);
        vd[s] = mask_at(rm, (b * Kst + s) * Lseq + l, u8) && mask_at(pm, b * Kst + s, u8);
        ln_w[s] = g_lognsw[b * Kst + s];
        swr[s]  = g_swr[bl * Kst + s];
    }

    float dot[Kst][Kst];
#pragma unroll
    for (int i = 0; i < Kst; i++) {
#pragma unroll
        for (int j = 0; j < Kst; j++) {
            float p = q[i].x * kk[j].x + q[i].y * kk[j].y;
#pragma unroll
            for (int o = 16; o; o >>= 1) p += __shfl_xor_sync(0xffffffffu, p, o);
            dot[i][j] = p;
        }
    }

    float a[Kst][Kst];
#pragma unroll
    for (int i = 0; i < Kst; i++) {
        float lm[Kst] = {0.f, 0.f, 0.f, 0.f};
        float m = -3.4e38f;
#pragma unroll
        for (int j = 0; j < Kst; j++) {
            if (vd[j]) {
                lm[j] = dot[i][j] * 0.125f + ln_w[j];
                m = fmaxf(m, lm[j]);
            }
        }
        float ssum = 0.f;
#pragma unroll
        for (int j = 0; j < Kst; j++) {
            float e = vd[j] ? expf(lm[j] - m) : 0.f;
            a[i][j] = e;
            ssum += e;
        }
        float invs = (ssum > 0.f) ? (1.f / ssum) : 0.f;
#pragma unroll
        for (int j = 0; j < Kst; j++) a[i][j] *= invs;
    }

    float px = 0.f, py = 0.f;
#pragma unroll
    for (int i = 0; i < Kst; i++) {
        float ox = 0.f, oy = 0.f;
#pragma unroll
        for (int j = 0; j < Kst; j++) {
            ox += a[i][j] * vv[j].x;
            oy += a[i][j] * vv[j].y;
        }
        px += swr[i] * ox;
        py += swr[i] * oy;
    }
    __nv_bfloat16 hx, lx, hy, ly;
    split2(px, hx, lx);
    split2(py, hy, ly);
    size_t ob = (size_t)bl * 1536 + col;
    *(__nv_bfloat162*)(g_AOs + ob)        = __nv_bfloat162(hx, hy);
    *(__nv_bfloat162*)(g_AOs + ob + 512)  = __nv_bfloat162(lx, ly);
    *(__nv_bfloat162*)(g_AOs + ob + 1024) = __nv_bfloat162(hx, hy);

    if (lane == 0) {
#pragma unroll
        for (int j = 0; j < Kst; j++)
            atomicAdd(&am[j], a[0][j] + a[1][j] + a[2][j] + a[3][j]);
    }
    __syncthreads();
    if (threadIdx.x < Kst)
        dout[OUT_AM + (size_t)bl * Kst + threadIdx.x] = am[threadIdx.x] * (1.f / 32.f);
}

// ---------------- block reduction ----------------
__device__ __forceinline__ float block_sum(float v, float* red) {
    int lane = threadIdx.x & 31, w = threadIdx.x >> 5;
#pragma unroll
    for (int o = 16; o; o >>= 1) v += __shfl_xor_sync(0xffffffffu, v, o);
    __syncthreads();
    if (lane == 0) red[w] = v;
    __syncthreads();
    if (threadIdx.x == 0) {
        float t = 0.f;
        int nw = (blockDim.x + 31) >> 5;
        for (int i = 0; i < nw; i++) t += red[i];
        red[8] = t;
    }
    __syncthreads();
    return red[8];
}

// ---------------- layernorm of gate_in (1536) -> split bf16 ----------------
__global__ void __launch_bounds__(256) ln_gatein_kernel(
    const float* __restrict__ dro, const float* __restrict__ g,
    const float* __restrict__ bb) {
    int bl = blockIdx.x;
    __shared__ float buf[D3];
    __shared__ float red[9];
    float s = 0.f;
    for (int c = threadIdx.x; c < D3; c += 256) {
        float v;
        if (c < Ddim)          v = dro[OUT_AP + (size_t)bl * Ddim + c];
        else if (c < 2 * Ddim) v = dro[OUT_WM + (size_t)bl * Ddim + (c - Ddim)];
        else                   v = dro[OUT_MF + (size_t)bl * Ddim + (c - 2 * Ddim)];
        buf[c] = v;
        s += v;
    }
    s = block_sum(s, red);
    float mu = s * (1.f / D3);
    float sq = 0.f;
    for (int c = threadIdx.x; c < D3; c += 256) {
        float d = buf[c] - mu;
        sq += d * d;
    }
    sq = block_sum(sq, red);
    float rs = rsqrtf(sq * (1.f / D3) + 1e-5f);
    for (int c = threadIdx.x; c < D3; c += 256) {
        float y = (buf[c] - mu) * rs * g[c] + bb[c];
        __nv_bfloat16 hi, lo;
        split2(y, hi, lo);
        size_t row = (size_t)bl * 4608;
        g_Gs[row + c] = hi;
        g_Gs[row + 1536 + c] = lo;
        g_Gs[row + 3072 + c] = hi;
    }
}

// ---------------- final fuse + layernorm(512) ----------------
__global__ void __launch_bounds__(256) ln_final_kernel(
    float* __restrict__ dout, const float* __restrict__ ng,
    const float* __restrict__ nb) {
    int bl = blockIdx.x;
    __shared__ float buf[Ddim];
    __shared__ float red[9];
    float s = 0.f;
    for (int d = threadIdx.x; d < Ddim; d += 256) {
        float gate = g_GATE[(size_t)bl * Ddim + d];
        float ap = dout[OUT_AP + (size_t)bl * Ddim + d];
        float wm = dout[OUT_WM + (size_t)bl * Ddim + d];
        float mf = dout[OUT_MF + (size_t)bl * Ddim + d];
        float y = gate * 0.5f * (ap + wm) + (1.f - gate) * mf + wm;
        buf[d] = y;
        s += y;
    }
    s = block_sum(s, red);
    float mu = s * (1.f / Ddim);
    float sq = 0.f;
    for (int d = threadIdx.x; d < Ddim; d += 256) {
        float dd = buf[d] - mu;
        sq += dd * dd;
    }
    sq = block_sum(sq, red);
    float rs = rsqrtf(sq * (1.f / Ddim) + 1e-5f);
    for (int d = threadIdx.x; d < Ddim; d += 256)
        dout[OUT_FUSED + (size_t)bl * Ddim + d] = (buf[d] - mu) * rs * ng[d] + nb[d];
}

// ---------------- launch ----------------
extern "C" void kernel_launch(void* const* d_in, const int* in_sizes, int n_in,
                              void* d_out, int out_size) {
    const float* sr    = (const float*)d_in[0];
    const void*  rmask = d_in[1];
    const float* sw    = (const float*)d_in[2];
    const int*   roles = (const int*)d_in[3];
    const void*  pmask = d_in[4];
    const float* remb  = (const float*)d_in[5];
    const float* Wq    = (const float*)d_in[6];
    const float* Wk    = (const float*)d_in[7];
    const float* Wv    = (const float*)d_in[8];
    const float* Wo    = (const float*)d_in[9];
    const float* ln1g  = (const float*)d_in[10];
    const float* ln1b  = (const float*)d_in[11];
    const float* Wg1   = (const float*)d_in[12];
    const float* bg1   = (const float*)d_in[13];
    const float* Wg2   = (const float*)d_in[14];
    const float* bg2   = (const float*)d_in[15];
    const float* ng    = (const float*)d_in[16];
    const float* nb    = (const float*)d_in[17];
    float* dout = (float*)d_out;

    __nv_bfloat16 *pXs, *pAOs, *pGs, *pH1s, *pWs1, *pWso, *pWsg1, *pWsg2;
    float *pQKV, *pGATE;
    cudaGetSymbolAddress((void**)&pXs, g_Xs);
    cudaGetSymbolAddress((void**)&pQKV, g_QKV);
    cudaGetSymbolAddress((void**)&pAOs, g_AOs);
    cudaGetSymbolAddress((void**)&pGs, g_Gs);
    cudaGetSymbolAddress((void**)&pH1s, g_H1s);
    cudaGetSymbolAddress((void**)&pGATE, g_GATE);
    cudaGetSymbolAddress((void**)&pWs1, g_Ws1);
    cudaGetSymbolAddress((void**)&pWso, g_Wso);
    cudaGetSymbolAddress((void**)&pWsg1, g_Wsg1);
    cudaGetSymbolAddress((void**)&pWsg2, g_Wsg2);

    cudaFuncSetAttribute(gemm_mma<0>, cudaFuncAttributeMaxDynamicSharedMemorySize, GSM_BYTES);
    cudaFuncSetAttribute(gemm_mma<1>, cudaFuncAttributeMaxDynamicSharedMemorySize, GSM_BYTES);
    cudaFuncSetAttribute(gemm_mma<2>, cudaFuncAttributeMaxDynamicSharedMemorySize, GSM_BYTES);

    detect_mask_kernel<<<1, 256>>>(rmask);
    nsw_kernel<<<1, 32>>>(sw, pmask, dout + OUT_NSW);
    build_x_kernel<<<BLn, 512>>>(sr, rmask, pmask, roles, remb, dout);

    split_w_kernel<<<(512 * 512 + 255) / 256, 256>>>(Wq, pWs1, 512, 512);
    split_w_kernel<<<(512 * 512 + 255) / 256, 256>>>(Wk, pWs1 + (size_t)512 * 1536, 512, 512);
    split_w_kernel<<<(512 * 512 + 255) / 256, 256>>>(Wv, pWs1 + (size_t)1024 * 1536, 512, 512);
    split_w_kernel<<<(512 * 512 + 255) / 256, 256>>>(Wo, pWso, 512, 512);
    split_w_kernel<<<(512 * 1536 + 255) / 256, 256>>>(Wg1, pWsg1, 512, 1536);
    split_w_kernel<<<(512 * 512 + 255) / 256, 256>>>(Wg2, pWsg2, 512, 512);

    // fused QKV: [32768 x 1536] = Xs @ Ws1^T
    {
        dim3 grid(1536 / 128, Tn / 128);
        gemm_mma<0><<<grid, 256, GSM_BYTES>>>(pXs, pWs1, nullptr, pQKV, nullptr, 1536, 1536);
    }

    attn_kernel<<<BLn, 256>>>(rmask, pmask, dout);

    // attn_pooled = AOs @ Wso^T  [8192 x 512]
    {
        dim3 grid(512 / 128, BLn / 128);
        gemm_mma<0><<<grid, 256, GSM_BYTES>>>(pAOs, pWso, nullptr, dout + OUT_AP, nullptr, 1536, 512);
    }

    ln_gatein_kernel<<<BLn, 256>>>(dout, ln1g, ln1b);

    // h = gelu(Gs @ Wsg1^T + bg1) -> split bf16
    {
        dim3 grid(512 / 128, BLn / 128);
        gemm_mma<1><<<grid, 256, GSM_BYTES>>>(pGs, pWsg1, bg1, nullptr, pH1s, 4608, 0);
    }
    // gate = sigmoid(H1s @ Wsg2^T + bg2)
    {
        dim3 grid(512 / 128, BLn / 128);
        gemm_mma<2><<<grid, 256, GSM_BYTES>>>(pH1s, pWsg2, bg2, pGATE, nullptr, 1536, 0);
    }

    ln_final_kernel<<<BLn, 256>>>(dout, ng, nb);
}

// round 4
// speedup vs baseline: 3.9189x; 1.6309x over previous
#include <cuda_runtime.h>
#include <cuda_bf16.h>
#include <math.h>
#include <stdint.h>

// ---------------- problem constants ----------------
#define Bdim 8
#define Kst 4
#define Lseq 1024
#define Ddim 512
#define Hn 8
#define HDdim 64
#define BLn 8192
#define Tn 32768
#define D3 1536

#define OUT_FUSED 0
#define OUT_AP    4194304
#define OUT_WM    8388608
#define OUT_MF    12582912
#define OUT_AM    16777216
#define OUT_NSW   16809984

// ---------------- device scratch ----------------
// split layout A-side rows: [hi(0:K) | lo(K:2K) | hi(2K:3K)]
// split layout B-side rows: [hi | hi | lo]  => A'.B' = hi.hi + lo.hi + hi.lo
__device__ __nv_bfloat16 g_Xs[(size_t)Tn * 1536];
__device__ float         g_QKV[(size_t)Tn * 1536];
__device__ __nv_bfloat16 g_AOs[(size_t)BLn * 1536];
__device__ __nv_bfloat16 g_Gs[(size_t)BLn * 4608];
__device__ __nv_bfloat16 g_H1s[(size_t)BLn * 1536];
__device__ float         g_GATE[(size_t)BLn * Ddim];
__device__ __nv_bfloat16 g_Ws1[1536 * 1536];
__device__ __nv_bfloat16 g_Wso[512 * 1536];
__device__ __nv_bfloat16 g_Wsg1[512 * 4608];
__device__ __nv_bfloat16 g_Wsg2[512 * 1536];
__device__ float g_swr[BLn * Kst];
__device__ float g_nsw[Bdim * Kst];
__device__ float g_lognsw[Bdim * Kst];
__device__ int   g_mask_u8;
__device__ int   g_cnt;               // compacted valid-row count
__device__ int   g_rowmap[Tn];        // compact slot -> original row

// ---------------- helpers ----------------
__device__ __forceinline__ uint32_t smem_u32(const void* p) {
    uint32_t a;
    asm("{ .reg .u64 t; cvta.to.shared.u64 t, %1; cvt.u32.u64 %0, t; }" : "=r"(a) : "l"(p));
    return a;
}
__device__ __forceinline__ void split2(float v, __nv_bfloat16& hi, __nv_bfloat16& lo) {
    hi = __float2bfloat16(v);
    lo = __float2bfloat16(v - __bfloat162float(hi));
}
__device__ __forceinline__ void ldsm_x4(uint32_t& r0, uint32_t& r1, uint32_t& r2,
                                        uint32_t& r3, uint32_t addr) {
    asm volatile("ldmatrix.sync.aligned.m8n8.x4.shared.b16 {%0,%1,%2,%3}, [%4];"
                 : "=r"(r0), "=r"(r1), "=r"(r2), "=r"(r3) : "r"(addr));
}
__device__ __forceinline__ void mma16816(float* c, const uint32_t* a, const uint32_t* b) {
    asm volatile(
        "mma.sync.aligned.m16n8k16.row.col.f32.bf16.bf16.f32 "
        "{%0,%1,%2,%3}, {%4,%5,%6,%7}, {%8,%9}, {%0,%1,%2,%3};"
        : "+f"(c[0]), "+f"(c[1]), "+f"(c[2]), "+f"(c[3])
        : "r"(a[0]), "r"(a[1]), "r"(a[2]), "r"(a[3]), "r"(b[0]), "r"(b[1]));
}
__device__ __forceinline__ uint32_t swz(uint32_t off) {
    return off ^ ((off >> 3) & 0x70);
}
__device__ __forceinline__ void cp_async16(uint32_t dst, const void* src) {
    asm volatile("cp.async.cg.shared.global [%0], [%1], 16;" :: "r"(dst), "l"(src));
}

// ---------------- mask dtype detection (+ counter reset) ----------------
__global__ void detect_mask_kernel(const void* rm) {
    const int* p = (const int*)rm;
    int bad = 0;
    for (int i = threadIdx.x; i < 8192; i += 256) {
        int v = p[i];
        if (v != 0 && v != 1) bad = 1;
    }
    bad = __syncthreads_or(bad);
    if (threadIdx.x == 0) {
        g_mask_u8 = bad;
        g_cnt = 0;
    }
}
__device__ __forceinline__ bool mask_at(const void* p, int idx, int u8) {
    return u8 ? (((const unsigned char*)p)[idx] != 0) : (((const int*)p)[idx] != 0);
}

// ---------------- nsw ----------------
__global__ void nsw_kernel(const float* __restrict__ sw, const void* __restrict__ pm,
                           float* __restrict__ out_nsw) {
    int b = threadIdx.x;
    if (b >= Bdim) return;
    int u8 = g_mask_u8;
    float w[Kst], pres[Kst];
    float denom = 0.f, psum = 0.f;
#pragma unroll
    for (int k = 0; k < Kst; k++) {
        pres[k] = mask_at(pm, b * Kst + k, u8) ? 1.f : 0.f;
        w[k] = sw[b * Kst + k] * pres[k];
        denom += w[k];
        psum += pres[k];
    }
#pragma unroll
    for (int k = 0; k < Kst; k++) {
        float nswk = (denom > 1e-8f) ? (w[k] / fmaxf(denom, 1e-8f))
                                     : (pres[k] / fmaxf(psum, 1.f));
        g_nsw[b * Kst + k] = nswk;
        g_lognsw[b * Kst + k] = logf(fmaxf(nswk, 1e-8f));
        out_nsw[b * Kst + k] = nswk;
    }
}

// ---------------- build split-x (compacted), weighted_mean, max_feat, swr ----------------
__global__ void __launch_bounds__(512) build_x_kernel(
    const float* __restrict__ sr, const void* __restrict__ rm,
    const void* __restrict__ pm, const int* __restrict__ roles,
    const float* __restrict__ remb, float* __restrict__ dout) {
    int bl = blockIdx.x;
    int b = bl >> 10;
    int l = bl & 1023;
    int d = threadIdx.x;
    int u8 = g_mask_u8;
    __shared__ int slots[Kst];

    bool vd[Kst];
    float swr[Kst];
    float ssum = 0.f;
#pragma unroll
    for (int k = 0; k < Kst; k++) {
        bool v = mask_at(rm, (b * Kst + k) * Lseq + l, u8) && mask_at(pm, b * Kst + k, u8);
        vd[k] = v;
        swr[k] = v ? g_nsw[b * Kst + k] : 0.f;
        ssum += swr[k];
    }
    if (d == 0) {
        int nv = 0;
#pragma unroll
        for (int k = 0; k < Kst; k++) nv += vd[k] ? 1 : 0;
        int base = nv ? atomicAdd(&g_cnt, nv) : 0;
#pragma unroll
        for (int k = 0; k < Kst; k++) {
            if (vd[k]) {
                slots[k] = base;
                g_rowmap[base] = bl * Kst + k;
                base++;
            } else slots[k] = -1;
        }
    }
    __syncthreads();
    float inv = 1.f / fmaxf(ssum, 1e-8f);

    float wm = 0.f, mx = -1e9f;
    bool any = false;
#pragma unroll
    for (int k = 0; k < Kst; k++) {
        swr[k] *= inv;
        float xv = 0.f;
        if (vd[k]) {
            int role = max(roles[b * Kst + k], 0);
            xv = sr[(((size_t)(b * Kst + k)) * Lseq + l) * Ddim + d] + remb[role * Ddim + d];
            any = true;
            mx = fmaxf(mx, xv);
            __nv_bfloat16 hi, lo;
            split2(xv, hi, lo);
            size_t row = (size_t)slots[k] * 1536;
            g_Xs[row + d] = hi;
            g_Xs[row + 512 + d] = lo;
            g_Xs[row + 1024 + d] = hi;
        }
        wm += swr[k] * xv;
    }
    dout[OUT_WM + (size_t)bl * Ddim + d] = wm;
    dout[OUT_MF + (size_t)bl * Ddim + d] = any ? mx : 0.f;
    if (d < Kst) g_swr[bl * Kst + d] = swr[d];
}

// ---------------- pad compacted rows to multiple of 128 with zeros ----------------
__global__ void pad_x_kernel() {
    int Mv = g_cnt;
    int padded = (Mv + 127) & ~127;
    int r = Mv + blockIdx.x;
    if (r >= padded) return;
    uint32_t* row = (uint32_t*)(g_Xs + (size_t)r * 1536);
    for (int i = threadIdx.x; i < 768; i += 256) row[i] = 0;
}

// ---------------- weight splitter: out[N x 3K] = [hi | hi | lo] ----------------
__global__ void split_w_kernel(const float* __restrict__ W, __nv_bfloat16* __restrict__ out,
                               int Nn, int Kk) {
    int idx = blockIdx.x * 256 + threadIdx.x;
    if (idx >= Nn * Kk) return;
    int n = idx / Kk, k = idx - n * Kk;
    float v = W[idx];
    __nv_bfloat16 hi, lo;
    split2(v, hi, lo);
    __nv_bfloat16* row = out + (size_t)n * 3 * Kk;
    row[k] = hi;
    row[Kk + k] = hi;
    row[2 * Kk + k] = lo;
}

// ---------------- HMMA bf16 GEMM, cp.async 3-stage pipeline ----------------
// C[M,N] = A[M,K'] @ B[N,K']^T. 128x128 CTA tile; 8 warps 2x4; warp 64x32.
// COMPACT: early-exit on dynamic M (g_cnt), epilogue scatters rows via g_rowmap.
// EPI 0: fp32 (ldc). EPI 1: bias+gelu -> split bf16 (ld 1536). EPI 2: bias+sigmoid (ld 512).
#define STAGES 3
#define GSM_BYTES (STAGES * 32768)

template <int EPI, bool COMPACT>
__global__ void __launch_bounds__(256) gemm_mma(
    const __nv_bfloat16* __restrict__ A, const __nv_bfloat16* __restrict__ B,
    const float* __restrict__ bias, float* __restrict__ Cf,
    __nv_bfloat16* __restrict__ Cb, int K, int ldc) {
    int Mv = 0;
    if (COMPACT) {
        Mv = g_cnt;
        int padded = (Mv + 127) & ~127;
        if ((int)(blockIdx.y * 128) >= padded) return;
    }
    extern __shared__ __align__(1024) char smem[];
    uint32_t sA0 = smem_u32(smem);
    int tid = threadIdx.x;
    int wid = tid >> 5, lane = tid & 31;
    const int wm = wid >> 2, wn = wid & 3;

    const size_t bm = (size_t)blockIdx.y * 128;
    const int bn = blockIdx.x * 128;
    const int seg = tid & 7;
    const int r0 = tid >> 3;

    const __nv_bfloat16* Ab = A + (bm + r0) * (size_t)K + seg * 8;
    const __nv_bfloat16* Bb = B + (size_t)(bn + r0) * K + seg * 8;
    const uint32_t swbase = swz(r0 * 128 + seg * 16);  // rows differ by 32 => swizzle-invariant offset

    auto copy_stage = [&](int c, int buf) {
        int kc = c << 6;
        uint32_t pa = sA0 + buf * 32768 + swbase;
#pragma unroll
        for (int i = 0; i < 4; i++) {
            cp_async16(pa + i * 32 * 128, Ab + (size_t)(i * 32) * K + kc);
            cp_async16(pa + 16384 + i * 32 * 128, Bb + (size_t)(i * 32) * K + kc);
        }
        asm volatile("cp.async.commit_group;" ::: "memory");
    };

    float acc[4][4][4];
#pragma unroll
    for (int i = 0; i < 4; i++)
#pragma unroll
        for (int j = 0; j < 4; j++)
#pragma unroll
            for (int q = 0; q < 4; q++) acc[i][j][q] = 0.f;

    const uint32_t aRow = wm * 64 + (lane & 15);
    const uint32_t aColB = (lane >> 4) << 4;
    const uint32_t bRow = wn * 32 + (lane & 7) + ((lane >> 4) << 3);
    const uint32_t bColB = ((lane >> 3) & 1) << 4;

    const int NC = K >> 6;
#pragma unroll
    for (int s = 0; s < STAGES - 1; s++)
        if (s < NC) copy_stage(s, s);

    for (int c = 0; c < NC; c++) {
        asm volatile("cp.async.wait_group %0;" :: "n"(STAGES - 2));
        __syncthreads();
        if (c + STAGES - 1 < NC) copy_stage(c + STAGES - 1, (c + STAGES - 1) % STAGES);

        uint32_t Abuf = sA0 + (c % STAGES) * 32768;
        uint32_t Bbuf = Abuf + 16384;
#pragma unroll
        for (int ks = 0; ks < 4; ks++) {
            uint32_t a[4][4], b[4][2];
#pragma unroll
            for (int mt = 0; mt < 4; mt++) {
                uint32_t off = (aRow + mt * 16) * 128 + ks * 32 + aColB;
                ldsm_x4(a[mt][0], a[mt][1], a[mt][2], a[mt][3], Abuf + swz(off));
            }
#pragma unroll
            for (int p = 0; p < 2; p++) {
                uint32_t off = (bRow + p * 16) * 128 + ks * 32 + bColB;
                ldsm_x4(b[2 * p][0], b[2 * p][1], b[2 * p + 1][0], b[2 * p + 1][1],
                        Bbuf + swz(off));
            }
#pragma unroll
            for (int mt = 0; mt < 4; mt++)
#pragma unroll
                for (int nt = 0; nt < 4; nt++)
                    mma16816(acc[mt][nt], a[mt], b[nt]);
        }
    }

    // epilogue
    const int g = lane >> 2, t = lane & 3;
#pragma unroll
    for (int mt = 0; mt < 4; mt++) {
#pragma unroll
        for (int half = 0; half < 2; half++) {
            size_t grow = bm + wm * 64 + mt * 16 + g + half * 8;
            size_t orow = grow;
            if (COMPACT) {
                if ((int)grow >= Mv) continue;
                orow = (size_t)g_rowmap[grow];
            }
#pragma unroll
            for (int nt = 0; nt < 4; nt++) {
                int col = bn + wn * 32 + nt * 8 + t * 2;
                float v0 = acc[mt][nt][half * 2 + 0];
                float v1 = acc[mt][nt][half * 2 + 1];
                if (EPI == 0) {
                    float2 o = make_float2(v0, v1);
                    *(float2*)(Cf + orow * (size_t)ldc + col) = o;
                } else if (EPI == 1) {
                    v0 += bias[col];
                    v1 += bias[col + 1];
                    v0 = 0.5f * v0 * (1.f + erff(v0 * 0.70710678118654752f));
                    v1 = 0.5f * v1 * (1.f + erff(v1 * 0.70710678118654752f));
                    __nv_bfloat16 h0, l0, h1, l1;
                    split2(v0, h0, l0);
                    split2(v1, h1, l1);
                    size_t o = orow * 1536 + col;
                    *(__nv_bfloat162*)(Cb + o)        = __nv_bfloat162(h0, h1);
                    *(__nv_bfloat162*)(Cb + o + 512)  = __nv_bfloat162(l0, l1);
                    *(__nv_bfloat162*)(Cb + o + 1024) = __nv_bfloat162(h0, h1);
                } else {
                    v0 += bias[col];
                    v1 += bias[col + 1];
                    float2 o;
                    o.x = 1.f / (1.f + expf(-v0));
                    o.y = 1.f / (1.f + expf(-v1));
                    *(float2*)(Cf + orow * 512 + col) = o;
                }
            }
        }
    }
}

// ---------------- attention: 4x4 per (b,l,h); pooled split output + attn_mean ----------------
__global__ void __launch_bounds__(256) attn_kernel(
    const void* __restrict__ rm, const void* __restrict__ pm,
    float* __restrict__ dout) {
    int bl = blockIdx.x;
    int b = bl >> 10;
    int l = bl & 1023;
    int warp = threadIdx.x >> 5;
    int lane = threadIdx.x & 31;
    __shared__ float am[Kst];
    if (threadIdx.x < Kst) am[threadIdx.x] = 0.f;
    __syncthreads();
    int u8 = g_mask_u8;

    float2 q[Kst], kk[Kst], vv[Kst];
    float ln_w[Kst], swr[Kst];
    bool vd[Kst];
    int col = warp * HDdim + lane * 2;
#pragma unroll
    for (int s = 0; s < Kst; s++) {
        vd[s] = mask_at(rm, (b * Kst + s) * Lseq + l, u8) && mask_at(pm, b * Kst + s, u8);
        if (vd[s]) {
            size_t rbase = (size_t)(bl * Kst + s) * 1536 + col;
            q[s]  = *(const float2*)(g_QKV + rbase);
            kk[s] = *(const float2*)(g_QKV + rbase + 512);
            vv[s] = *(const float2*)(g_QKV + rbase + 1024);
        } else {
            q[s] = kk[s] = vv[s] = make_float2(0.f, 0.f);
        }
        ln_w[s] = g_lognsw[b * Kst + s];
        swr[s]  = g_swr[bl * Kst + s];
    }

    float dot[Kst][Kst];
#pragma unroll
    for (int i = 0; i < Kst; i++) {
#pragma unroll
        for (int j = 0; j < Kst; j++) {
            float p = q[i].x * kk[j].x + q[i].y * kk[j].y;
#pragma unroll
            for (int o = 16; o; o >>= 1) p += __shfl_xor_sync(0xffffffffu, p, o);
            dot[i][j] = p;
        }
    }

    float a[Kst][Kst];
#pragma unroll
    for (int i = 0; i < Kst; i++) {
        float lm[Kst] = {0.f, 0.f, 0.f, 0.f};
        float m = -3.4e38f;
#pragma unroll
        for (int j = 0; j < Kst; j++) {
            if (vd[j]) {
                lm[j] = dot[i][j] * 0.125f + ln_w[j];
                m = fmaxf(m, lm[j]);
            }
        }
        float ssum = 0.f;
#pragma unroll
        for (int j = 0; j < Kst; j++) {
            float e = vd[j] ? expf(lm[j] - m) : 0.f;
            a[i][j] = e;
            ssum += e;
        }
        float invs = (ssum > 0.f) ? (1.f / ssum) : 0.f;
#pragma unroll
        for (int j = 0; j < Kst; j++) a[i][j] *= invs;
    }

    float px = 0.f, py = 0.f;
#pragma unroll
    for (int i = 0; i < Kst; i++) {
        float ox = 0.f, oy = 0.f;
#pragma unroll
        for (int j = 0; j < Kst; j++) {
            ox += a[i][j] * vv[j].x;
            oy += a[i][j] * vv[j].y;
        }
        px += swr[i] * ox;
        py += swr[i] * oy;
    }
    __nv_bfloat16 hx, lx, hy, ly;
    split2(px, hx, lx);
    split2(py, hy, ly);
    size_t ob = (size_t)bl * 1536 + col;
    *(__nv_bfloat162*)(g_AOs + ob)        = __nv_bfloat162(hx, hy);
    *(__nv_bfloat162*)(g_AOs + ob + 512)  = __nv_bfloat162(lx, ly);
    *(__nv_bfloat162*)(g_AOs + ob + 1024) = __nv_bfloat162(hx, hy);

    if (lane == 0) {
#pragma unroll
        for (int j = 0; j < Kst; j++)
            atomicAdd(&am[j], a[0][j] + a[1][j] + a[2][j] + a[3][j]);
    }
    __syncthreads();
    if (threadIdx.x < Kst)
        dout[OUT_AM + (size_t)bl * Kst + threadIdx.x] = am[threadIdx.x] * (1.f / 32.f);
}

// ---------------- block reduction ----------------
__device__ __forceinline__ float block_sum(float v, float* red) {
    int lane = threadIdx.x & 31, w = threadIdx.x >> 5;
#pragma unroll
    for (int o = 16; o; o >>= 1) v += __shfl_xor_sync(0xffffffffu, v, o);
    __syncthreads();
    if (lane == 0) red[w] = v;
    __syncthreads();
    if (threadIdx.x == 0) {
        float t = 0.f;
        int nw = (blockDim.x + 31) >> 5;
        for (int i = 0; i < nw; i++) t += red[i];
        red[8] = t;
    }
    __syncthreads();
    return red[8];
}

// ---------------- layernorm of gate_in (1536) -> split bf16 ----------------
__global__ void __launch_bounds__(256) ln_gatein_kernel(
    const float* __restrict__ dro, const float* __restrict__ g,
    const float* __restrict__ bb) {
    int bl = blockIdx.x;
    __shared__ float buf[D3];
    __shared__ float red[9];
    float s = 0.f;
    for (int c = threadIdx.x; c < D3; c += 256) {
        float v;
        if (c < Ddim)          v = dro[OUT_AP + (size_t)bl * Ddim + c];
        else if (c < 2 * Ddim) v = dro[OUT_WM + (size_t)bl * Ddim + (c - Ddim)];
        else                   v = dro[OUT_MF + (size_t)bl * Ddim + (c - 2 * Ddim)];
        buf[c] = v;
        s += v;
    }
    s = block_sum(s, red);
    float mu = s * (1.f / D3);
    float sq = 0.f;
    for (int c = threadIdx.x; c < D3; c += 256) {
        float d = buf[c] - mu;
        sq += d * d;
    }
    sq = block_sum(sq, red);
    float rs = rsqrtf(sq * (1.f / D3) + 1e-5f);
    for (int c = threadIdx.x; c < D3; c += 256) {
        float y = (buf[c] - mu) * rs * g[c] + bb[c];
        __nv_bfloat16 hi, lo;
        split2(y, hi, lo);
        size_t row = (size_t)bl * 4608;
        g_Gs[row + c] = hi;
        g_Gs[row + 1536 + c] = lo;
        g_Gs[row + 3072 + c] = hi;
    }
}

// ---------------- final fuse + layernorm(512) ----------------
__global__ void __launch_bounds__(256) ln_final_kernel(
    float* __restrict__ dout, const float* __restrict__ ng,
    const float* __restrict__ nb) {
    int bl = blockIdx.x;
    __shared__ float buf[Ddim];
    __shared__ float red[9];
    float s = 0.f;
    for (int d = threadIdx.x; d < Ddim; d += 256) {
        float gate = g_GATE[(size_t)bl * Ddim + d];
        float ap = dout[OUT_AP + (size_t)bl * Ddim + d];
        float wm = dout[OUT_WM + (size_t)bl * Ddim + d];
        float mf = dout[OUT_MF + (size_t)bl * Ddim + d];
        float y = gate * 0.5f * (ap + wm) + (1.f - gate) * mf + wm;
        buf[d] = y;
        s += y;
    }
    s = block_sum(s, red);
    float mu = s * (1.f / Ddim);
    float sq = 0.f;
    for (int d = threadIdx.x; d < Ddim; d += 256) {
        float dd = buf[d] - mu;
        sq += dd * dd;
    }
    sq = block_sum(sq, red);
    float rs = rsqrtf(sq * (1.f / Ddim) + 1e-5f);
    for (int d = threadIdx.x; d < Ddim; d += 256)
        dout[OUT_FUSED + (size_t)bl * Ddim + d] = (buf[d] - mu) * rs * ng[d] + nb[d];
}

// ---------------- launch ----------------
extern "C" void kernel_launch(void* const* d_in, const int* in_sizes, int n_in,
                              void* d_out, int out_size) {
    const float* sr    = (const float*)d_in[0];
    const void*  rmask = d_in[1];
    const float* sw    = (const float*)d_in[2];
    const int*   roles = (const int*)d_in[3];
    const void*  pmask = d_in[4];
    const float* remb  = (const float*)d_in[5];
    const float* Wq    = (const float*)d_in[6];
    const float* Wk    = (const float*)d_in[7];
    const float* Wv    = (const float*)d_in[8];
    const float* Wo    = (const float*)d_in[9];
    const float* ln1g  = (const float*)d_in[10];
    const float* ln1b  = (const float*)d_in[11];
    const float* Wg1   = (const float*)d_in[12];
    const float* bg1   = (const float*)d_in[13];
    const float* Wg2   = (const float*)d_in[14];
    const float* bg2   = (const float*)d_in[15];
    const float* ng    = (const float*)d_in[16];
    const float* nb    = (const float*)d_in[17];
    float* dout = (float*)d_out;

    __nv_bfloat16 *pXs, *pAOs, *pGs, *pH1s, *pWs1, *pWso, *pWsg1, *pWsg2;
    float *pQKV, *pGATE;
    cudaGetSymbolAddress((void**)&pXs, g_Xs);
    cudaGetSymbolAddress((void**)&pQKV, g_QKV);
    cudaGetSymbolAddress((void**)&pAOs, g_AOs);
    cudaGetSymbolAddress((void**)&pGs, g_Gs);
    cudaGetSymbolAddress((void**)&pH1s, g_H1s);
    cudaGetSymbolAddress((void**)&pGATE, g_GATE);
    cudaGetSymbolAddress((void**)&pWs1, g_Ws1);
    cudaGetSymbolAddress((void**)&pWso, g_Wso);
    cudaGetSymbolAddress((void**)&pWsg1, g_Wsg1);
    cudaGetSymbolAddress((void**)&pWsg2, g_Wsg2);

    cudaFuncSetAttribute(gemm_mma<0, true>, cudaFuncAttributeMaxDynamicSharedMemorySize, GSM_BYTES);
    cudaFuncSetAttribute(gemm_mma<0, false>, cudaFuncAttributeMaxDynamicSharedMemorySize, GSM_BYTES);
    cudaFuncSetAttribute(gemm_mma<1, false>, cudaFuncAttributeMaxDynamicSharedMemorySize, GSM_BYTES);
    cudaFuncSetAttribute(gemm_mma<2, false>, cudaFuncAttributeMaxDynamicSharedMemorySize, GSM_BYTES);

    detect_mask_kernel<<<1, 256>>>(rmask);
    nsw_kernel<<<1, 32>>>(sw, pmask, dout + OUT_NSW);
    build_x_kernel<<<BLn, 512>>>(sr, rmask, pmask, roles, remb, dout);
    pad_x_kernel<<<128, 256>>>();

    split_w_kernel<<<(512 * 512 + 255) / 256, 256>>>(Wq, pWs1, 512, 512);
    split_w_kernel<<<(512 * 512 + 255) / 256, 256>>>(Wk, pWs1 + (size_t)512 * 1536, 512, 512);
    split_w_kernel<<<(512 * 512 + 255) / 256, 256>>>(Wv, pWs1 + (size_t)1024 * 1536, 512, 512);
    split_w_kernel<<<(512 * 512 + 255) / 256, 256>>>(Wo, pWso, 512, 512);
    split_w_kernel<<<(512 * 1536 + 255) / 256, 256>>>(Wg1, pWsg1, 512, 1536);
    split_w_kernel<<<(512 * 512 + 255) / 256, 256>>>(Wg2, pWsg2, 512, 512);

    // fused QKV on compacted rows: [Mv x 1536] = Xs @ Ws1^T, scatter rows
    {
        dim3 grid(1536 / 128, Tn / 128);
        gemm_mma<0, true><<<grid, 256, GSM_BYTES>>>(pXs, pWs1, nullptr, pQKV, nullptr, 1536, 1536);
    }

    attn_kernel<<<BLn, 256>>>(rmask, pmask, dout);

    // attn_pooled = AOs @ Wso^T  [8192 x 512]
    {
        dim3 grid(512 / 128, BLn / 128);
        gemm_mma<0, false><<<grid, 256, GSM_BYTES>>>(pAOs, pWso, nullptr, dout + OUT_AP, nullptr, 1536, 512);
    }

    ln_gatein_kernel<<<BLn, 256>>>(dout, ln1g, ln1b);

    // h = gelu(Gs @ Wsg1^T + bg1) -> split bf16
    {
        dim3 grid(512 / 128, BLn / 128);
        gemm_mma<1, false><<<grid, 256, GSM_BYTES>>>(pGs, pWsg1, bg1, nullptr, pH1s, 4608, 0);
    }
    // gate = sigmoid(H1s @ Wsg2^T + bg2)
    {
        dim3 grid(512 / 128, BLn / 128);
        gemm_mma<2, false><<<grid, 256, GSM_BYTES>>>(pH1s, pWsg2, bg2, pGATE, nullptr, 1536, 0);
    }

    ln_final_kernel<<<BLn, 256>>>(dout, ng, nb);
}